// round 12
// baseline (speedup 1.0000x reference)
#include <cuda_runtime.h>
#include <cuda_bf16.h>

// Single-launch producer/consumer:
//   blocks 0..255   (producers): 8 rows each, warp-per-row gather ->
//                    g_s[row][128], g_deg[row]; fence; atomicAdd(flag[group]).
//   blocks 256..383 (consumers): 2 groups of 8 rows each; spin on flag==8,
//                    fence, 8-row register-blocked GEMM vs L1-resident W,
//                    bias*deg + relu, store; reset flag (graph-replay safe).
// Producers never wait => deadlock-free under any scheduling.

#define MJ    128
#define FE    64
#define FC    128
#define NROW  2048
#define NGRP  256            // 8-row groups
#define PBLK  256            // producer blocks
#define CBLK  128            // consumer blocks

__device__ float g_s[NROW][FC];      // 1 MB scratch (static device: allowed)
__device__ float g_deg[NROW];
__device__ int   g_flag[NGRP];       // zero-init; returns to 0 each launch

__global__ __launch_bounds__(256, 4)
void gcn_pc_kernel(const float* __restrict__ sf1,
                   const float* __restrict__ sf2,
                   const float* __restrict__ adj,
                   const float* __restrict__ W,
                   const float* __restrict__ bias,
                   float* __restrict__ out)
{
    __shared__ int    s_off[8][136];
    __shared__ float  s_val[8][136];
    __shared__ float  s_sm[8][FC];
    __shared__ float  s_deg[8];
    __shared__ float4 red4[8][8][32];

    const int bid  = blockIdx.x;
    const int t    = threadIdx.x;
    const int w    = t >> 5;
    const int lane = t & 31;

    if (bid < PBLK) {
        // ================= PRODUCER: warp w owns row bid*8+w =================
        const int row = bid * 8 + w;

        // adj row -> in-warp compaction (R5-proven), zero-padded to 8-batches
        const float* arow = adj + (size_t)row * MJ;
        const float a0 = __ldg(arow + lane);
        const float a1 = __ldg(arow + lane + 32);
        const float a2 = __ldg(arow + lane + 64);
        const float a3 = __ldg(arow + lane + 96);
        const unsigned b0 = __ballot_sync(0xffffffffu, a0 != 0.0f);
        const unsigned b1 = __ballot_sync(0xffffffffu, a1 != 0.0f);
        const unsigned b2 = __ballot_sync(0xffffffffu, a2 != 0.0f);
        const unsigned b3 = __ballot_sync(0xffffffffu, a3 != 0.0f);
        const int c0 = __popc(b0), c1 = __popc(b1), c2 = __popc(b2);
        const int nnz = c0 + c1 + c2 + __popc(b3);
        const unsigned lm = (1u << lane) - 1u;
        if (a0 != 0.0f) { const int p = __popc(b0 & lm);
                          s_off[w][p] = (lane     ) * FE; s_val[w][p] = a0; }
        if (a1 != 0.0f) { const int p = c0 + __popc(b1 & lm);
                          s_off[w][p] = (lane + 32) * FE; s_val[w][p] = a1; }
        if (a2 != 0.0f) { const int p = c0 + c1 + __popc(b2 & lm);
                          s_off[w][p] = (lane + 64) * FE; s_val[w][p] = a2; }
        if (a3 != 0.0f) { const int p = c0 + c1 + c2 + __popc(b3 & lm);
                          s_off[w][p] = (lane + 96) * FE; s_val[w][p] = a3; }
        if (lane < 8) { s_off[w][nnz + lane] = 0; s_val[w][nnz + lane] = 0.0f; }
        {
            float d = (a0 + a1) + (a2 + a3);
            #pragma unroll
            for (int off = 16; off > 0; off >>= 1)
                d += __shfl_down_sync(0xffffffffu, d, off);
            if (lane == 0) g_deg[row] = d;
        }
        __syncwarp();

        // gather: lanes 0-15 sf1 (ch 0..63), lanes 16-31 sf2 (ch 64..127)
        const float* base = ((lane < 16) ? sf1 : sf2)
                          + (size_t)row * MJ * FE + (lane & 15) * 4;
        float4 acc0 = make_float4(0.f, 0.f, 0.f, 0.f);
        float4 acc1 = make_float4(0.f, 0.f, 0.f, 0.f);
        for (int k = 0; k < nnz; k += 8) {
            const int o0 = s_off[w][k    ], o1 = s_off[w][k + 1];
            const int o2 = s_off[w][k + 2], o3 = s_off[w][k + 3];
            const int o4 = s_off[w][k + 4], o5 = s_off[w][k + 5];
            const int o6 = s_off[w][k + 6], o7 = s_off[w][k + 7];
            const float4 v0 = __ldcs(reinterpret_cast<const float4*>(base + o0));
            const float4 v1 = __ldcs(reinterpret_cast<const float4*>(base + o1));
            const float4 v2 = __ldcs(reinterpret_cast<const float4*>(base + o2));
            const float4 v3 = __ldcs(reinterpret_cast<const float4*>(base + o3));
            const float4 v4 = __ldcs(reinterpret_cast<const float4*>(base + o4));
            const float4 v5 = __ldcs(reinterpret_cast<const float4*>(base + o5));
            const float4 v6 = __ldcs(reinterpret_cast<const float4*>(base + o6));
            const float4 v7 = __ldcs(reinterpret_cast<const float4*>(base + o7));
            const float q0 = s_val[w][k    ], q1 = s_val[w][k + 1];
            const float q2 = s_val[w][k + 2], q3 = s_val[w][k + 3];
            const float q4 = s_val[w][k + 4], q5 = s_val[w][k + 5];
            const float q6 = s_val[w][k + 6], q7 = s_val[w][k + 7];
            acc0.x += q0 * v0.x; acc0.y += q0 * v0.y; acc0.z += q0 * v0.z; acc0.w += q0 * v0.w;
            acc1.x += q1 * v1.x; acc1.y += q1 * v1.y; acc1.z += q1 * v1.z; acc1.w += q1 * v1.w;
            acc0.x += q2 * v2.x; acc0.y += q2 * v2.y; acc0.z += q2 * v2.z; acc0.w += q2 * v2.w;
            acc1.x += q3 * v3.x; acc1.y += q3 * v3.y; acc1.z += q3 * v3.z; acc1.w += q3 * v3.w;
            acc0.x += q4 * v4.x; acc0.y += q4 * v4.y; acc0.z += q4 * v4.z; acc0.w += q4 * v4.w;
            acc1.x += q5 * v5.x; acc1.y += q5 * v5.y; acc1.z += q5 * v5.z; acc1.w += q5 * v5.w;
            acc0.x += q6 * v6.x; acc0.y += q6 * v6.y; acc0.z += q6 * v6.z; acc0.w += q6 * v6.w;
            acc1.x += q7 * v7.x; acc1.y += q7 * v7.y; acc1.z += q7 * v7.z; acc1.w += q7 * v7.w;
        }
        float4 s4;
        s4.x = acc0.x + acc1.x; s4.y = acc0.y + acc1.y;
        s4.z = acc0.z + acc1.z; s4.w = acc0.w + acc1.w;
        reinterpret_cast<float4*>(g_s[row])[lane] = s4;

        // publish: all lanes fence their own stores, then lane 0 signals
        __threadfence();
        __syncwarp();
        if (lane == 0) atomicAdd(&g_flag[bid], 1);

    } else {
        // ================= CONSUMER: 2 groups of 8 rows =================
        const int cb = bid - PBLK;           // 0..127
        #pragma unroll
        for (int gi = 0; gi < 2; ++gi) {
            const int g    = cb + gi * CBLK; // group id = producer bid
            const int row0 = g * 8;

            if (t == 0) {                    // wait for all 8 row-warps
                while (atomicAdd(&g_flag[g], 0) < 8) __nanosleep(64);
            }
            __syncthreads();
            __threadfence();                 // order flag-observe before reads

            // load + stage s vectors and degrees (L2-coherent, bypass L1)
            {
                const int r = t >> 5, q = t & 31;
                const float4 p = __ldcg(&reinterpret_cast<const float4*>(g_s[row0 + r])[q]);
                reinterpret_cast<float4*>(s_sm[r])[q] = p;
                if (q == 0) s_deg[r] = __ldcg(&g_deg[row0 + r]);
            }
            __syncthreads();
            if (t == 0) g_flag[g] = 0;       // reset for next graph replay

            // GEMM: warp w owns f-slice 16; 8-row register blocking
            {
                const int f0 = w * 16;
                const float4* W4 = reinterpret_cast<const float4*>(W);
                float4 acc[8];
                #pragma unroll
                for (int r = 0; r < 8; ++r) acc[r] = make_float4(0.f, 0.f, 0.f, 0.f);
                #pragma unroll
                for (int kk = 0; kk < 16; ++kk) {
                    const int f = f0 + kk;
                    const float4 wv = W4[f * 32 + lane];   // L1-resident
                    #pragma unroll
                    for (int r = 0; r < 8; ++r) {
                        const float s = s_sm[r][f];
                        acc[r].x += s * wv.x; acc[r].y += s * wv.y;
                        acc[r].z += s * wv.z; acc[r].w += s * wv.w;
                    }
                }
                #pragma unroll
                for (int r = 0; r < 8; ++r) red4[w][r][lane] = acc[r];
            }
            __syncthreads();

            // combine 8 f-slices + bias*deg + relu + store
            {
                const int r = t >> 5, q = t & 31;
                float4 rs = red4[0][r][q];
                #pragma unroll
                for (int sl = 1; sl < 8; ++sl) {
                    const float4 p = red4[sl][r][q];
                    rs.x += p.x; rs.y += p.y; rs.z += p.z; rs.w += p.w;
                }
                const float4 bb = reinterpret_cast<const float4*>(bias)[q];
                const float  d  = s_deg[r];
                float4 o4;
                o4.x = fmaxf(rs.x + bb.x * d, 0.0f);
                o4.y = fmaxf(rs.y + bb.y * d, 0.0f);
                o4.z = fmaxf(rs.z + bb.z * d, 0.0f);
                o4.w = fmaxf(rs.w + bb.w * d, 0.0f);
                reinterpret_cast<float4*>(out)[(size_t)(row0 + r) * 32 + q] = o4;
            }
            __syncthreads();                 // safe reuse of s_sm/red4
        }
    }
}

extern "C" void kernel_launch(void* const* d_in, const int* in_sizes, int n_in,
                              void* d_out, int out_size)
{
    const float* sf1  = (const float*)d_in[0];  // (16,128,128,64)
    const float* sf2  = (const float*)d_in[1];  // (16,128,128,64)
    const float* adj  = (const float*)d_in[2];  // (16,128,128)
    const float* W    = (const float*)d_in[3];  // (128,128)
    const float* bias = (const float*)d_in[4];  // (128,)
    float* out = (float*)d_out;                 // (16,128,128)

    gcn_pc_kernel<<<PBLK + CBLK, 256>>>(sf1, sf2, adj, W, bias, out);
}

// round 13
// speedup vs baseline: 1.8456x; 1.8456x over previous
#include <cuda_runtime.h>
#include <cuda_bf16.h>

// Two-kernel split.
// K1 (gather, barrier-free, proven ~6.1 TB/s): spart[h][row][f], degp[h][row]
// K2 (lean epilogue GEMM): transposed-s smem (1 broadcast LDS.128/k-step) +
//     packed fma.rn.f32x2 (row-pair accumulators) -> 3x fewer issue slots/FLOP.

#define MJ   128
#define FE   64
#define FC   128
#define NROW 2048

__device__ float g_spart[2][NROW][FC];   // 2 MB scratch (static device: allowed)
__device__ float g_degp[2][NROW];

// ---------------------------------------------------------------------------
// Kernel 1: pure gather — UNCHANGED from round 8.
// ---------------------------------------------------------------------------
__global__ __launch_bounds__(256, 4)
void gcn_gather_kernel(const float* __restrict__ sf1,
                       const float* __restrict__ sf2,
                       const float* __restrict__ adj)
{
    __shared__ int   s_off[8][72];
    __shared__ float s_val[8][72];

    const int t    = threadIdx.x;
    const int w    = t >> 5;
    const int lane = t & 31;
    const int pr   = w >> 1;
    const int h    = w & 1;
    const int row  = blockIdx.x * 4 + pr;

    const float* arow = adj + (size_t)row * MJ + h * 64;
    const float a0 = __ldg(arow + lane);
    const float a1 = __ldg(arow + lane + 32);
    const unsigned b0 = __ballot_sync(0xffffffffu, a0 != 0.0f);
    const unsigned b1 = __ballot_sync(0xffffffffu, a1 != 0.0f);
    const int c0  = __popc(b0);
    const int nnz = c0 + __popc(b1);
    const unsigned lm = (1u << lane) - 1u;
    if (a0 != 0.0f) { const int p = __popc(b0 & lm);
                      s_off[w][p] = (h * 64 + lane     ) * FE; s_val[w][p] = a0; }
    if (a1 != 0.0f) { const int p = c0 + __popc(b1 & lm);
                      s_off[w][p] = (h * 64 + lane + 32) * FE; s_val[w][p] = a1; }
    if (lane < 8) {
        s_off[w][nnz + lane] = 0;
        s_val[w][nnz + lane] = 0.0f;
    }
    {
        float d = a0 + a1;
        #pragma unroll
        for (int off = 16; off > 0; off >>= 1)
            d += __shfl_down_sync(0xffffffffu, d, off);
        if (lane == 0) g_degp[h][row] = d;
    }
    __syncwarp();

    const float* base = ((lane < 16) ? sf1 : sf2)
                      + (size_t)row * MJ * FE + (lane & 15) * 4;
    float4 acc0 = make_float4(0.f, 0.f, 0.f, 0.f);
    float4 acc1 = make_float4(0.f, 0.f, 0.f, 0.f);
    for (int k = 0; k < nnz; k += 8) {
        const int o0 = s_off[w][k    ], o1 = s_off[w][k + 1];
        const int o2 = s_off[w][k + 2], o3 = s_off[w][k + 3];
        const int o4 = s_off[w][k + 4], o5 = s_off[w][k + 5];
        const int o6 = s_off[w][k + 6], o7 = s_off[w][k + 7];
        const float4 v0 = __ldcs(reinterpret_cast<const float4*>(base + o0));
        const float4 v1 = __ldcs(reinterpret_cast<const float4*>(base + o1));
        const float4 v2 = __ldcs(reinterpret_cast<const float4*>(base + o2));
        const float4 v3 = __ldcs(reinterpret_cast<const float4*>(base + o3));
        const float4 v4 = __ldcs(reinterpret_cast<const float4*>(base + o4));
        const float4 v5 = __ldcs(reinterpret_cast<const float4*>(base + o5));
        const float4 v6 = __ldcs(reinterpret_cast<const float4*>(base + o6));
        const float4 v7 = __ldcs(reinterpret_cast<const float4*>(base + o7));
        const float q0 = s_val[w][k    ], q1 = s_val[w][k + 1];
        const float q2 = s_val[w][k + 2], q3 = s_val[w][k + 3];
        const float q4 = s_val[w][k + 4], q5 = s_val[w][k + 5];
        const float q6 = s_val[w][k + 6], q7 = s_val[w][k + 7];
        acc0.x += q0 * v0.x; acc0.y += q0 * v0.y; acc0.z += q0 * v0.z; acc0.w += q0 * v0.w;
        acc1.x += q1 * v1.x; acc1.y += q1 * v1.y; acc1.z += q1 * v1.z; acc1.w += q1 * v1.w;
        acc0.x += q2 * v2.x; acc0.y += q2 * v2.y; acc0.z += q2 * v2.z; acc0.w += q2 * v2.w;
        acc1.x += q3 * v3.x; acc1.y += q3 * v3.y; acc1.z += q3 * v3.z; acc1.w += q3 * v3.w;
        acc0.x += q4 * v4.x; acc0.y += q4 * v4.y; acc0.z += q4 * v4.z; acc0.w += q4 * v4.w;
        acc1.x += q5 * v5.x; acc1.y += q5 * v5.y; acc1.z += q5 * v5.z; acc1.w += q5 * v5.w;
        acc0.x += q6 * v6.x; acc0.y += q6 * v6.y; acc0.z += q6 * v6.z; acc0.w += q6 * v6.w;
        acc1.x += q7 * v7.x; acc1.y += q7 * v7.y; acc1.z += q7 * v7.z; acc1.w += q7 * v7.w;
    }
    float4 s4;
    s4.x = acc0.x + acc1.x; s4.y = acc0.y + acc1.y;
    s4.z = acc0.z + acc1.z; s4.w = acc0.w + acc1.w;
    reinterpret_cast<float4*>(g_spart[h][row])[lane] = s4;
}

// ---------------------------------------------------------------------------
// Kernel 2: lean epilogue GEMM.
// grid 512, 4 rows/block. s transposed in smem: s4[f] = {r0,r1,r2,r3}.
// Per k-step/thread: 1 LDS.128 (broadcast, pre-packed row pairs) +
// 1 LDG.128 (W) + 4 dup-packs + 8 fma.rn.f32x2  (32 FMA in 14 instrs).
// ---------------------------------------------------------------------------
__global__ __launch_bounds__(256, 6)
void gcn_gemm_kernel(const float* __restrict__ W,
                     const float* __restrict__ bias,
                     float* __restrict__ out)
{
    __shared__ float4 s4[FC];               // s4[f] = s of rows 0..3 at feat f
    __shared__ float  s_deg[4];
    __shared__ float4 red4[8][4][32];       // [k-slice][row][quad]

    const int t    = threadIdx.x;
    const int w    = t >> 5;
    const int lane = t & 31;
    const int row0 = blockIdx.x * 4;

    // ---- stage: transpose s into s4[f], combine halves (coalesced reads) ----
    if (t < FC) {
        const int f = t;
        float4 v;
        v.x = g_spart[0][row0 + 0][f] + g_spart[1][row0 + 0][f];
        v.y = g_spart[0][row0 + 1][f] + g_spart[1][row0 + 1][f];
        v.z = g_spart[0][row0 + 2][f] + g_spart[1][row0 + 2][f];
        v.w = g_spart[0][row0 + 3][f] + g_spart[1][row0 + 3][f];
        s4[f] = v;
        if (f < 4) s_deg[f] = g_degp[0][row0 + f] + g_degp[1][row0 + f];
    }
    __syncthreads();

    // ---- GEMM: warp w owns f-slice [w*16, w*16+16) ----
    // acc01[c] = packed {row0,row1} output component c; acc23 likewise.
    {
        const int f0 = w * 16;
        const float4* W4 = reinterpret_cast<const float4*>(W);
        unsigned long long acc01[4] = {0ull, 0ull, 0ull, 0ull};  // {0.f,0.f}
        unsigned long long acc23[4] = {0ull, 0ull, 0ull, 0ull};
        #pragma unroll
        for (int kk = 0; kk < 16; ++kk) {
            const int f = f0 + kk;
            // LDS.128 broadcast: s pairs already packed {r0,r1},{r2,r3}
            unsigned long long s01, s23;
            asm volatile("ld.shared.v2.u64 {%0, %1}, [%2];"
                         : "=l"(s01), "=l"(s23)
                         : "r"((unsigned)__cvta_generic_to_shared(&s4[f])));
            const float4 wv = W4[f * 32 + lane];     // L1/L2-resident
            unsigned long long wd;
            asm("mov.b64 %0, {%1, %1};" : "=l"(wd) : "f"(wv.x));
            asm("fma.rn.f32x2 %0, %1, %2, %0;" : "+l"(acc01[0]) : "l"(s01), "l"(wd));
            asm("fma.rn.f32x2 %0, %1, %2, %0;" : "+l"(acc23[0]) : "l"(s23), "l"(wd));
            asm("mov.b64 %0, {%1, %1};" : "=l"(wd) : "f"(wv.y));
            asm("fma.rn.f32x2 %0, %1, %2, %0;" : "+l"(acc01[1]) : "l"(s01), "l"(wd));
            asm("fma.rn.f32x2 %0, %1, %2, %0;" : "+l"(acc23[1]) : "l"(s23), "l"(wd));
            asm("mov.b64 %0, {%1, %1};" : "=l"(wd) : "f"(wv.z));
            asm("fma.rn.f32x2 %0, %1, %2, %0;" : "+l"(acc01[2]) : "l"(s01), "l"(wd));
            asm("fma.rn.f32x2 %0, %1, %2, %0;" : "+l"(acc23[2]) : "l"(s23), "l"(wd));
            asm("mov.b64 %0, {%1, %1};" : "=l"(wd) : "f"(wv.w));
            asm("fma.rn.f32x2 %0, %1, %2, %0;" : "+l"(acc01[3]) : "l"(s01), "l"(wd));
            asm("fma.rn.f32x2 %0, %1, %2, %0;" : "+l"(acc23[3]) : "l"(s23), "l"(wd));
        }
        // unpack: acc01[c] = {row0_c, row1_c}; acc23[c] = {row2_c, row3_c}
        float4 r0v, r1v, r2v, r3v;
        asm("mov.b64 {%0, %1}, %2;" : "=f"(r0v.x), "=f"(r1v.x) : "l"(acc01[0]));
        asm("mov.b64 {%0, %1}, %2;" : "=f"(r0v.y), "=f"(r1v.y) : "l"(acc01[1]));
        asm("mov.b64 {%0, %1}, %2;" : "=f"(r0v.z), "=f"(r1v.z) : "l"(acc01[2]));
        asm("mov.b64 {%0, %1}, %2;" : "=f"(r0v.w), "=f"(r1v.w) : "l"(acc01[3]));
        asm("mov.b64 {%0, %1}, %2;" : "=f"(r2v.x), "=f"(r3v.x) : "l"(acc23[0]));
        asm("mov.b64 {%0, %1}, %2;" : "=f"(r2v.y), "=f"(r3v.y) : "l"(acc23[1]));
        asm("mov.b64 {%0, %1}, %2;" : "=f"(r2v.z), "=f"(r3v.z) : "l"(acc23[2]));
        asm("mov.b64 {%0, %1}, %2;" : "=f"(r2v.w), "=f"(r3v.w) : "l"(acc23[3]));
        red4[w][0][lane] = r0v;
        red4[w][1][lane] = r1v;
        red4[w][2][lane] = r2v;
        red4[w][3][lane] = r3v;
    }
    __syncthreads();

    // ---- combine 8 f-slices + bias*deg + relu + store ----
    if (t < 128) {
        const int r = t >> 5, q = t & 31;
        float4 rs = red4[0][r][q];
        #pragma unroll
        for (int sl = 1; sl < 8; ++sl) {
            const float4 p = red4[sl][r][q];
            rs.x += p.x; rs.y += p.y; rs.z += p.z; rs.w += p.w;
        }
        const float4 bb = reinterpret_cast<const float4*>(bias)[q];
        const float  d  = s_deg[r];
        float4 o4;
        o4.x = fmaxf(rs.x + bb.x * d, 0.0f);
        o4.y = fmaxf(rs.y + bb.y * d, 0.0f);
        o4.z = fmaxf(rs.z + bb.z * d, 0.0f);
        o4.w = fmaxf(rs.w + bb.w * d, 0.0f);
        reinterpret_cast<float4*>(out)[(size_t)(row0 + r) * 32 + q] = o4;
    }
}

extern "C" void kernel_launch(void* const* d_in, const int* in_sizes, int n_in,
                              void* d_out, int out_size)
{
    const float* sf1  = (const float*)d_in[0];  // (16,128,128,64)
    const float* sf2  = (const float*)d_in[1];  // (16,128,128,64)
    const float* adj  = (const float*)d_in[2];  // (16,128,128)
    const float* W    = (const float*)d_in[3];  // (128,128)
    const float* bias = (const float*)d_in[4];  // (128,)
    float* out = (float*)d_out;                 // (16,128,128)

    gcn_gather_kernel<<<NROW / 4, 256>>>(sf1, sf2, adj);
    gcn_gemm_kernel<<<NROW / 4, 256>>>(W, bias, out);
}

// round 14
// speedup vs baseline: 2.2147x; 1.2000x over previous
#include <cuda_runtime.h>
#include <cuda_bf16.h>

// Fused (single launch), R7 gather + R13 lean GEMM.
// Block: 256 thr = 8 warps, 4 rows. Gather: 2 warps/row (64-wide j-half,
// in-warp compaction zero-padded to 8-deep batches). Then transpose s into
// s4[f]={r0,r1,r2,r3} and run a packed-FFMA2 GEMM: per k-step ONE broadcast
// LDS.128 + ONE W LDG.128 + 8 fma.rn.f32x2 (32 FMA in ~14 instrs).

#define RPB   4       // rows per block
#define NW    8       // warps per block
#define MJ    128
#define FE    64
#define FC    128

__global__ __launch_bounds__(256, 4)
void gcn_fused_kernel(const float* __restrict__ sf1,
                      const float* __restrict__ sf2,
                      const float* __restrict__ adj,
                      const float* __restrict__ W,
                      const float* __restrict__ bias,
                      float* __restrict__ out)
{
    __shared__ int    s_off[NW][72];        // compacted j*FE offsets (+pad)
    __shared__ float  s_val[NW][72];        // compacted adjacency values
    __shared__ float  s_part[NW][FC];       // per-(row,half) partial s
    __shared__ float  s_degp[NW];
    __shared__ float4 s4[FC];               // s4[f] = {row0..row3} at feat f
    __shared__ float4 red4[NW][RPB][32];    // [k-slice][row][quad]

    const int t    = threadIdx.x;
    const int w    = t >> 5;
    const int lane = t & 31;
    const int pr   = w >> 1;                // row within block
    const int h    = w & 1;                 // j-half
    const int row0 = blockIdx.x * RPB;
    const int row  = row0 + pr;

    // ---- Phase 1 (warp-local): 64 adj values -> compaction, zero-padded ----
    const float* arow = adj + (size_t)row * MJ + h * 64;
    const float a0 = __ldg(arow + lane);
    const float a1 = __ldg(arow + lane + 32);
    const unsigned b0 = __ballot_sync(0xffffffffu, a0 != 0.0f);
    const unsigned b1 = __ballot_sync(0xffffffffu, a1 != 0.0f);
    const int c0  = __popc(b0);
    const int nnz = c0 + __popc(b1);
    const unsigned lm = (1u << lane) - 1u;
    if (a0 != 0.0f) { const int p = __popc(b0 & lm);
                      s_off[w][p] = (h * 64 + lane     ) * FE; s_val[w][p] = a0; }
    if (a1 != 0.0f) { const int p = c0 + __popc(b1 & lm);
                      s_off[w][p] = (h * 64 + lane + 32) * FE; s_val[w][p] = a1; }
    if (lane < 8) {
        s_off[w][nnz + lane] = 0;
        s_val[w][nnz + lane] = 0.0f;
    }
    {
        float d = a0 + a1;
        #pragma unroll
        for (int off = 16; off > 0; off >>= 1)
            d += __shfl_down_sync(0xffffffffu, d, off);
        if (lane == 0) s_degp[w] = d;
    }
    __syncwarp();

    // ---- Phase 2 (warp-local): gather, full 8-deep batches ----
    {
        const float* base = ((lane < 16) ? sf1 : sf2)
                          + (size_t)row * MJ * FE + (lane & 15) * 4;
        float4 acc0 = make_float4(0.f, 0.f, 0.f, 0.f);
        float4 acc1 = make_float4(0.f, 0.f, 0.f, 0.f);
        for (int k = 0; k < nnz; k += 8) {
            const int o0 = s_off[w][k    ], o1 = s_off[w][k + 1];
            const int o2 = s_off[w][k + 2], o3 = s_off[w][k + 3];
            const int o4 = s_off[w][k + 4], o5 = s_off[w][k + 5];
            const int o6 = s_off[w][k + 6], o7 = s_off[w][k + 7];
            const float4 v0 = __ldcs(reinterpret_cast<const float4*>(base + o0));
            const float4 v1 = __ldcs(reinterpret_cast<const float4*>(base + o1));
            const float4 v2 = __ldcs(reinterpret_cast<const float4*>(base + o2));
            const float4 v3 = __ldcs(reinterpret_cast<const float4*>(base + o3));
            const float4 v4 = __ldcs(reinterpret_cast<const float4*>(base + o4));
            const float4 v5 = __ldcs(reinterpret_cast<const float4*>(base + o5));
            const float4 v6 = __ldcs(reinterpret_cast<const float4*>(base + o6));
            const float4 v7 = __ldcs(reinterpret_cast<const float4*>(base + o7));
            const float q0 = s_val[w][k    ], q1 = s_val[w][k + 1];
            const float q2 = s_val[w][k + 2], q3 = s_val[w][k + 3];
            const float q4 = s_val[w][k + 4], q5 = s_val[w][k + 5];
            const float q6 = s_val[w][k + 6], q7 = s_val[w][k + 7];
            acc0.x += q0 * v0.x; acc0.y += q0 * v0.y; acc0.z += q0 * v0.z; acc0.w += q0 * v0.w;
            acc1.x += q1 * v1.x; acc1.y += q1 * v1.y; acc1.z += q1 * v1.z; acc1.w += q1 * v1.w;
            acc0.x += q2 * v2.x; acc0.y += q2 * v2.y; acc0.z += q2 * v2.z; acc0.w += q2 * v2.w;
            acc1.x += q3 * v3.x; acc1.y += q3 * v3.y; acc1.z += q3 * v3.z; acc1.w += q3 * v3.w;
            acc0.x += q4 * v4.x; acc0.y += q4 * v4.y; acc0.z += q4 * v4.z; acc0.w += q4 * v4.w;
            acc1.x += q5 * v5.x; acc1.y += q5 * v5.y; acc1.z += q5 * v5.z; acc1.w += q5 * v5.w;
            acc0.x += q6 * v6.x; acc0.y += q6 * v6.y; acc0.z += q6 * v6.z; acc0.w += q6 * v6.w;
            acc1.x += q7 * v7.x; acc1.y += q7 * v7.y; acc1.z += q7 * v7.z; acc1.w += q7 * v7.w;
        }
        float4 sv;
        sv.x = acc0.x + acc1.x; sv.y = acc0.y + acc1.y;
        sv.z = acc0.z + acc1.z; sv.w = acc0.w + acc1.w;
        reinterpret_cast<float4*>(s_part[w])[lane] = sv;
    }
    __syncthreads();

    // ---- Phase 3a: transpose+combine into s4[f] = {r0,r1,r2,r3} ----
    if (t < FC) {
        const int f = t;
        float4 v;
        v.x = s_part[0][f] + s_part[1][f];
        v.y = s_part[2][f] + s_part[3][f];
        v.z = s_part[4][f] + s_part[5][f];
        v.w = s_part[6][f] + s_part[7][f];
        s4[f] = v;
    }
    __syncthreads();

    // ---- Phase 3b: lean GEMM. Warp w owns f-slice [w*16, w*16+16) ----
    {
        const int f0 = w * 16;
        const float4* W4 = reinterpret_cast<const float4*>(W);
        unsigned long long acc01[4] = {0ull, 0ull, 0ull, 0ull};
        unsigned long long acc23[4] = {0ull, 0ull, 0ull, 0ull};
        #pragma unroll
        for (int kk = 0; kk < 16; ++kk) {
            const int f = f0 + kk;
            unsigned long long s01, s23;   // packed {r0,r1}, {r2,r3}
            asm volatile("ld.shared.v2.u64 {%0, %1}, [%2];"
                         : "=l"(s01), "=l"(s23)
                         : "r"((unsigned)__cvta_generic_to_shared(&s4[f])));
            const float4 wv = W4[f * 32 + lane];     // L1/L2-resident
            unsigned long long wd;
            asm("mov.b64 %0, {%1, %1};" : "=l"(wd) : "f"(wv.x));
            asm("fma.rn.f32x2 %0, %1, %2, %0;" : "+l"(acc01[0]) : "l"(s01), "l"(wd));
            asm("fma.rn.f32x2 %0, %1, %2, %0;" : "+l"(acc23[0]) : "l"(s23), "l"(wd));
            asm("mov.b64 %0, {%1, %1};" : "=l"(wd) : "f"(wv.y));
            asm("fma.rn.f32x2 %0, %1, %2, %0;" : "+l"(acc01[1]) : "l"(s01), "l"(wd));
            asm("fma.rn.f32x2 %0, %1, %2, %0;" : "+l"(acc23[1]) : "l"(s23), "l"(wd));
            asm("mov.b64 %0, {%1, %1};" : "=l"(wd) : "f"(wv.z));
            asm("fma.rn.f32x2 %0, %1, %2, %0;" : "+l"(acc01[2]) : "l"(s01), "l"(wd));
            asm("fma.rn.f32x2 %0, %1, %2, %0;" : "+l"(acc23[2]) : "l"(s23), "l"(wd));
            asm("mov.b64 %0, {%1, %1};" : "=l"(wd) : "f"(wv.w));
            asm("fma.rn.f32x2 %0, %1, %2, %0;" : "+l"(acc01[3]) : "l"(s01), "l"(wd));
            asm("fma.rn.f32x2 %0, %1, %2, %0;" : "+l"(acc23[3]) : "l"(s23), "l"(wd));
        }
        float4 r0v, r1v, r2v, r3v;
        asm("mov.b64 {%0, %1}, %2;" : "=f"(r0v.x), "=f"(r1v.x) : "l"(acc01[0]));
        asm("mov.b64 {%0, %1}, %2;" : "=f"(r0v.y), "=f"(r1v.y) : "l"(acc01[1]));
        asm("mov.b64 {%0, %1}, %2;" : "=f"(r0v.z), "=f"(r1v.z) : "l"(acc01[2]));
        asm("mov.b64 {%0, %1}, %2;" : "=f"(r0v.w), "=f"(r1v.w) : "l"(acc01[3]));
        asm("mov.b64 {%0, %1}, %2;" : "=f"(r2v.x), "=f"(r3v.x) : "l"(acc23[0]));
        asm("mov.b64 {%0, %1}, %2;" : "=f"(r2v.y), "=f"(r3v.y) : "l"(acc23[1]));
        asm("mov.b64 {%0, %1}, %2;" : "=f"(r2v.z), "=f"(r3v.z) : "l"(acc23[2]));
        asm("mov.b64 {%0, %1}, %2;" : "=f"(r2v.w), "=f"(r3v.w) : "l"(acc23[3]));
        red4[w][0][lane] = r0v;
        red4[w][1][lane] = r1v;
        red4[w][2][lane] = r2v;
        red4[w][3][lane] = r3v;
    }
    __syncthreads();

    // ---- Phase 4: combine 8 f-slices + bias*deg + relu + store ----
    if (t < 128) {
        const int r = t >> 5, q = t & 31;
        float4 rs = red4[0][r][q];
        #pragma unroll
        for (int sl = 1; sl < 8; ++sl) {
            const float4 p = red4[sl][r][q];
            rs.x += p.x; rs.y += p.y; rs.z += p.z; rs.w += p.w;
        }
        const float4 bb = reinterpret_cast<const float4*>(bias)[q];
        const float  d  = s_degp[2 * r] + s_degp[2 * r + 1];
        float4 o4;
        o4.x = fmaxf(rs.x + bb.x * d, 0.0f);
        o4.y = fmaxf(rs.y + bb.y * d, 0.0f);
        o4.z = fmaxf(rs.z + bb.z * d, 0.0f);
        o4.w = fmaxf(rs.w + bb.w * d, 0.0f);
        reinterpret_cast<float4*>(out)[(size_t)(row0 + r) * 32 + q] = o4;
    }
}

extern "C" void kernel_launch(void* const* d_in, const int* in_sizes, int n_in,
                              void* d_out, int out_size)
{
    const float* sf1  = (const float*)d_in[0];  // (16,128,128,64)
    const float* sf2  = (const float*)d_in[1];  // (16,128,128,64)
    const float* adj  = (const float*)d_in[2];  // (16,128,128)
    const float* W    = (const float*)d_in[3];  // (128,128)
    const float* bias = (const float*)d_in[4];  // (128,)
    float* out = (float*)d_out;                 // (16,128,128)

    gcn_fused_kernel<<<2048 / RPB, 256>>>(sf1, sf2, adj, W, bias, out);
}